// round 4
// baseline (speedup 1.0000x reference)
#include <cuda_runtime.h>
#include <cuda_bf16.h>
#include <math.h>
#include <float.h>
#include <stdint.h>

#define B_   2
#define T_   2048
#define C_   2048
#define H_   16
#define KVH_ 4
#define HD_  128
#define M_   (B_*T_)           // 4096
#define K3_  6144              // 3 * 2048 (split-K)
#define QKV_LD 3072

// ---------------- scratch ----------------
__device__ __nv_bfloat16 g_xs [(size_t)M_ * K3_];
__device__ __nv_bfloat16 g_wb1[(size_t)3072 * K3_];
__device__ __nv_bfloat16 g_wb2[(size_t)2048 * K3_];
__device__ __nv_bfloat16 g_ys [(size_t)M_ * K3_];
__device__ float g_qkv[(size_t)M_ * QKV_LD];
__device__ float g_y  [(size_t)M_ * 2048];

// ---------------- helpers ----------------
__device__ __forceinline__ void split2(float v, __nv_bfloat16& h, __nv_bfloat16& l) {
    h = __float2bfloat16_rn(v);
    l = __float2bfloat16_rn(v - __bfloat162float(h));
}
__device__ __forceinline__ uint32_t smem_u32(const void* p) {
    uint32_t a;
    asm("{ .reg .u64 t; cvta.to.shared.u64 t, %1; cvt.u32.u64 %0, t; }" : "=r"(a) : "l"(p));
    return a;
}
__device__ __forceinline__ uint32_t packbf2(float x, float y) {
    __nv_bfloat162 t = __floats2bfloat162_rn(x, y);
    return *(uint32_t*)&t;
}
#define LDMX4(r0, r1, r2, r3, addr) \
    asm volatile("ldmatrix.sync.aligned.m8n8.x4.shared.b16 {%0,%1,%2,%3}, [%4];" \
        : "=r"(r0), "=r"(r1), "=r"(r2), "=r"(r3) : "r"(addr))
#define MMA16816(c, a0, a1, a2, a3, b0, b1) \
    asm volatile("mma.sync.aligned.m16n8k16.row.col.f32.bf16.bf16.f32 " \
        "{%0,%1,%2,%3}, {%4,%5,%6,%7}, {%8,%9}, {%0,%1,%2,%3};" \
        : "+f"((c)[0]), "+f"((c)[1]), "+f"((c)[2]), "+f"((c)[3]) \
        : "r"(a0), "r"(a1), "r"(a2), "r"(a3), "r"(b0), "r"(b1))

// ---------------- split kernels ----------------
__global__ __launch_bounds__(256)
void split_a_kernel(const float* __restrict__ src, __nv_bfloat16* __restrict__ dst) {
    int idx = blockIdx.x * 256 + threadIdx.x;
    int m = idx >> 9;
    int k = (idx & 511) << 2;
    float4 v = *(const float4*)(src + (size_t)m * 2048 + k);
    __nv_bfloat16 h0, h1, h2, h3, l0, l1, l2, l3;
    split2(v.x, h0, l0); split2(v.y, h1, l1);
    split2(v.z, h2, l2); split2(v.w, h3, l3);
    __nv_bfloat162 H0 = __halves2bfloat162(h0, h1), H1 = __halves2bfloat162(h2, h3);
    __nv_bfloat162 L0 = __halves2bfloat162(l0, l1), L1 = __halves2bfloat162(l2, l3);
    __nv_bfloat162* d0 = (__nv_bfloat162*)(dst + (size_t)m * K3_ + k);
    d0[0] = H0; d0[1] = H1;
    __nv_bfloat162* d1 = (__nv_bfloat162*)(dst + (size_t)m * K3_ + 2048 + k);
    d1[0] = L0; d1[1] = L1;
    __nv_bfloat162* d2 = (__nv_bfloat162*)(dst + (size_t)m * K3_ + 4096 + k);
    d2[0] = H0; d2[1] = H1;
}

__global__ __launch_bounds__(256)
void tsplit_b_kernel(const float* __restrict__ src, __nv_bfloat16* __restrict__ dst, int Ncols) {
    __shared__ float t[32][33];
    const int n0 = blockIdx.x * 32, k0 = blockIdx.y * 32;
    const int tx = threadIdx.x, ty = threadIdx.y;
#pragma unroll
    for (int i = 0; i < 4; i++)
        t[ty + i * 8][tx] = src[(size_t)(k0 + ty + i * 8) * Ncols + n0 + tx];
    __syncthreads();
#pragma unroll
    for (int i = 0; i < 4; i++) {
        float v = t[tx][ty + i * 8];
        __nv_bfloat16 h, l;
        split2(v, h, l);
        __nv_bfloat16* row = dst + (size_t)(n0 + ty + i * 8) * K3_ + k0 + tx;
        row[0]    = h;
        row[2048] = h;
        row[4096] = l;
    }
}

// ---------------- bf16 mma.sync GEMM (as round 3) ----------------
#define SMPAD 80

__global__ __launch_bounds__(256)
void gemm_bf16(const __nv_bfloat16* __restrict__ A, const __nv_bfloat16* __restrict__ Bt,
               float* __restrict__ C, int N) {
    __shared__ __align__(16) uint8_t sm[4 * 128 * SMPAD];
    const uint32_t smb = smem_u32(sm);

    const int tid = threadIdx.x;
    const int lane = tid & 31, wid = tid >> 5;
    const int wm = wid >> 1, wn = wid & 1;
    const int m0 = blockIdx.y * 128, n0 = blockIdx.x * 128;

    const int row_g = tid >> 2;
    const int c16   = tid & 3;

    float acc[2][8][4];
#pragma unroll
    for (int i = 0; i < 2; i++)
#pragma unroll
        for (int j = 0; j < 8; j++)
#pragma unroll
            for (int r = 0; r < 4; r++) acc[i][j][r] = 0.0f;

    const int nK = K3_ / 32;

    {
        const __nv_bfloat16* ap = A  + (size_t)(m0 + row_g) * K3_ + c16 * 8;
        const __nv_bfloat16* bp = Bt + (size_t)(n0 + row_g) * K3_ + c16 * 8;
        uint4 a0 = *(const uint4*)ap;
        uint4 a1 = *(const uint4*)(ap + (size_t)64 * K3_);
        uint4 b0 = *(const uint4*)bp;
        uint4 b1 = *(const uint4*)(bp + (size_t)64 * K3_);
        *(uint4*)(sm + row_g * SMPAD + c16 * 16)                     = a0;
        *(uint4*)(sm + (row_g + 64) * SMPAD + c16 * 16)              = a1;
        *(uint4*)(sm + 2 * 128 * SMPAD + row_g * SMPAD + c16 * 16)        = b0;
        *(uint4*)(sm + 2 * 128 * SMPAD + (row_g + 64) * SMPAD + c16 * 16) = b1;
    }
    __syncthreads();

    const int lj = lane >> 3, lr = lane & 7;
    const uint32_t a_row_off = (uint32_t)((wm * 32 + ((lj & 1) << 3) + lr) * SMPAD + ((lj >> 1) << 4));
    const uint32_t b_row_off = (uint32_t)((wn * 64 + ((lj >> 1) << 3) + lr) * SMPAD + ((lj & 1) << 4));

    for (int it = 0; it < nK; it++) {
        const int buf = it & 1;
        uint4 na0, na1, nb0, nb1;
        if (it + 1 < nK) {
            const int k0 = (it + 1) << 5;
            const __nv_bfloat16* ap = A  + (size_t)(m0 + row_g) * K3_ + k0 + c16 * 8;
            const __nv_bfloat16* bp = Bt + (size_t)(n0 + row_g) * K3_ + k0 + c16 * 8;
            na0 = *(const uint4*)ap;
            na1 = *(const uint4*)(ap + (size_t)64 * K3_);
            nb0 = *(const uint4*)bp;
            nb1 = *(const uint4*)(bp + (size_t)64 * K3_);
        }

        const uint32_t sA = smb + buf * 128 * SMPAD;
        const uint32_t sB = smb + (2 + buf) * 128 * SMPAD;
#pragma unroll
        for (int kk = 0; kk < 2; kk++) {
            uint32_t af[2][4];
#pragma unroll
            for (int i = 0; i < 2; i++)
                LDMX4(af[i][0], af[i][1], af[i][2], af[i][3],
                      sA + a_row_off + i * 16 * SMPAD + kk * 32);
            uint32_t bf[8][2];
#pragma unroll
            for (int p = 0; p < 4; p++) {
                uint32_t r0, r1, r2, r3;
                LDMX4(r0, r1, r2, r3, sB + b_row_off + p * 16 * SMPAD + kk * 32);
                bf[2 * p][0] = r0; bf[2 * p][1] = r1;
                bf[2 * p + 1][0] = r2; bf[2 * p + 1][1] = r3;
            }
#pragma unroll
            for (int i = 0; i < 2; i++)
#pragma unroll
                for (int j = 0; j < 8; j++)
                    MMA16816(acc[i][j], af[i][0], af[i][1], af[i][2], af[i][3],
                             bf[j][0], bf[j][1]);
        }
        __syncthreads();
        if (it + 1 < nK) {
            const int nbuf = (it + 1) & 1;
            uint8_t* dA = sm + nbuf * 128 * SMPAD;
            uint8_t* dB = sm + (2 + nbuf) * 128 * SMPAD;
            *(uint4*)(dA + row_g * SMPAD + c16 * 16)        = na0;
            *(uint4*)(dA + (row_g + 64) * SMPAD + c16 * 16) = na1;
            *(uint4*)(dB + row_g * SMPAD + c16 * 16)        = nb0;
            *(uint4*)(dB + (row_g + 64) * SMPAD + c16 * 16) = nb1;
            __syncthreads();
        }
    }

    const int cr = lane >> 2, cc = (lane & 3) << 1;
#pragma unroll
    for (int i = 0; i < 2; i++) {
        const int mrow = m0 + wm * 32 + i * 16 + cr;
#pragma unroll
        for (int j = 0; j < 8; j++) {
            const int col = n0 + wn * 64 + j * 8 + cc;
            *(float2*)(C + (size_t)mrow * N + col)       = make_float2(acc[i][j][0], acc[i][j][1]);
            *(float2*)(C + (size_t)(mrow + 8) * N + col) = make_float2(acc[i][j][2], acc[i][j][3]);
        }
    }
}

// ---------------- RoPE + RMSNorm ----------------
__global__ __launch_bounds__(32)
void rope_rms_kernel(float* __restrict__ qkv,
                     const float* __restrict__ cosp, const float* __restrict__ sinp) {
    const int n  = blockIdx.x;
    const int bt = n / (H_ + KVH_);
    const int hh = n - bt * (H_ + KVH_);
    float* p = qkv + (size_t)bt * QKV_LD +
               ((hh < H_) ? (size_t)hh * 128 : (size_t)(2048 + (hh - H_) * 128));
    const int t = bt & (T_ - 1);
    const int l = threadIdx.x;

    float o1[2], o2[2];
    float ss = 0.0f;
#pragma unroll
    for (int u = 0; u < 2; u++) {
        int d = l + u * 32;
        float x1 = p[d];
        float x2 = p[d + 64];
        float c = cosp[t * 64 + d];
        float s = sinp[t * 64 + d];
        o1[u] = x1 * c + x2 * s;
        o2[u] = x2 * c - x1 * s;
        ss += o1[u] * o1[u] + o2[u] * o2[u];
    }
#pragma unroll
    for (int off = 16; off > 0; off >>= 1)
        ss += __shfl_xor_sync(0xffffffffu, ss, off);
    float r = rsqrtf(ss * (1.0f / 128.0f) + 1e-5f);
#pragma unroll
    for (int u = 0; u < 2; u++) {
        int d = l + u * 32;
        p[d]      = o1[u] * r;
        p[d + 64] = o2[u] * r;
    }
}

// ---------------- tensor-core flash attention ----------------
// 64 q-rows per CTA, 8 warps (4m x 2n). hi/lo split on all MMA operands.
#define AQS 528          // Q/K smem row stride bytes ([hi 256B | lo 256B])
#define AVS 272          // Vt row stride bytes ([Vh 128B | Vl 128B])
#define SM_Q 0
#define SM_K 33792
#define SM_V 67584
#define SM_RED 102400
#define ATT_SMEM 103424
#define ATT_SCALE 0.08838834764831845f

__global__ __launch_bounds__(256)
void attn_mma_kernel(const float* __restrict__ qkv, float* __restrict__ y) {
    extern __shared__ uint8_t sm[];
    const uint32_t smb = smem_u32(sm);
    float* redmax = (float*)(sm + SM_RED);          // [2][64]
    float* redsum = (float*)(sm + SM_RED + 512);    // [2][64]

    const int tid = threadIdx.x;
    const int lane = tid & 31, wid = tid >> 5;
    const int wm = wid >> 1, wn = wid & 1;
    const int qtile = 31 - blockIdx.x;              // heavy tiles first
    const int bh = blockIdx.y;
    const int b  = bh >> 4;
    const int h  = bh & 15;
    const int kv = h >> 2;
    const int q0 = qtile * 64;

    const int crow = tid >> 2;            // 0..63 (convert row)
    const int cc0  = (tid & 3) * 32;      // col chunk base

    // ---- convert Q tile (64x128 fp32 -> hi|lo bf16) ----
    {
        const float* qp = qkv + (size_t)(b * T_ + q0 + crow) * QKV_LD + h * 128 + cc0;
        uint8_t* qrow = sm + SM_Q + crow * AQS;
#pragma unroll
        for (int i = 0; i < 8; i++) {
            float4 v = *(const float4*)(qp + i * 4);
            __nv_bfloat16 h0, h1, h2, h3, l0, l1, l2, l3;
            split2(v.x, h0, l0); split2(v.y, h1, l1);
            split2(v.z, h2, l2); split2(v.w, h3, l3);
            int c = cc0 + i * 4;
            *(__nv_bfloat162*)(qrow + 2 * c)           = __halves2bfloat162(h0, h1);
            *(__nv_bfloat162*)(qrow + 2 * c + 4)       = __halves2bfloat162(h2, h3);
            *(__nv_bfloat162*)(qrow + 256 + 2 * c)     = __halves2bfloat162(l0, l1);
            *(__nv_bfloat162*)(qrow + 256 + 2 * c + 4) = __halves2bfloat162(l2, l3);
        }
    }

    // ldmatrix base addresses
    const int lj = lane >> 3, lr = lane & 7;
    const uint32_t a_off = smb + SM_Q + (uint32_t)((wm * 16 + ((lj & 1) << 3) + lr) * AQS + ((lj >> 1) << 4));
    uint32_t b_off[2];
#pragma unroll
    for (int p = 0; p < 2; p++)
        b_off[p] = smb + SM_K + (uint32_t)((wn * 32 + p * 16 + ((lj >> 1) << 3) + lr) * AQS + ((lj & 1) << 4));
    uint32_t v_off[8];
#pragma unroll
    for (int p = 0; p < 8; p++)
        v_off[p] = smb + SM_V + (uint32_t)((p * 16 + ((lj >> 1) << 3) + lr) * AVS + ((lj & 1) << 4));

    // softmax state
    const int ra = lane >> 2;
    const int row_a = wm * 16 + ra, row_b = row_a + 8;
    const int colb = wn * 32 + 2 * (lane & 3);
    float m_a = -FLT_MAX, m_b = -FLT_MAX, l_a = 0.0f, l_b = 0.0f;

    float o[16][4];
#pragma unroll
    for (int j = 0; j < 16; j++)
#pragma unroll
        for (int r = 0; r < 4; r++) o[j][r] = 0.0f;

    for (int jt = 0; jt <= qtile; jt++) {
        const int j0 = jt * 64;
        __syncthreads();   // K/V smem free (prev PV done); also orders Q stores on jt=0
        // ---- convert K,V tiles ----
        {
            const float* kp = qkv + (size_t)(b * T_ + j0 + crow) * QKV_LD + 2048 + kv * 128 + cc0;
            const float* vp = qkv + (size_t)(b * T_ + j0 + crow) * QKV_LD + 2560 + kv * 128 + cc0;
            uint8_t* krow = sm + SM_K + crow * AQS;
#pragma unroll
            for (int i = 0; i < 8; i++) {
                float4 vk = *(const float4*)(kp + i * 4);
                __nv_bfloat16 h0, h1, h2, h3, l0, l1, l2, l3;
                split2(vk.x, h0, l0); split2(vk.y, h1, l1);
                split2(vk.z, h2, l2); split2(vk.w, h3, l3);
                int c = cc0 + i * 4;
                *(__nv_bfloat162*)(krow + 2 * c)           = __halves2bfloat162(h0, h1);
                *(__nv_bfloat162*)(krow + 2 * c + 4)       = __halves2bfloat162(h2, h3);
                *(__nv_bfloat162*)(krow + 256 + 2 * c)     = __halves2bfloat162(l0, l1);
                *(__nv_bfloat162*)(krow + 256 + 2 * c + 4) = __halves2bfloat162(l2, l3);

                float4 vv = *(const float4*)(vp + i * 4);
                float vals[4] = {vv.x, vv.y, vv.z, vv.w};
#pragma unroll
                for (int e = 0; e < 4; e++) {
                    int d = cc0 + i * 4 + e;
                    __nv_bfloat16 hh, ll;
                    split2(vals[e], hh, ll);
                    *(__nv_bfloat16*)(sm + SM_V + d * AVS + 2 * crow)       = hh;
                    *(__nv_bfloat16*)(sm + SM_V + d * AVS + 128 + 2 * crow) = ll;
                }
            }
        }
        __syncthreads();

        // ---- S = Q' K'^T  (3 split segments) ----
        float s_[4][4];
#pragma unroll
        for (int j = 0; j < 4; j++)
#pragma unroll
            for (int r = 0; r < 4; r++) s_[j][r] = 0.0f;

#pragma unroll
        for (int seg = 0; seg < 3; seg++) {
            const uint32_t abase = (seg == 1) ? 256u : 0u;
            const uint32_t bbase = (seg == 2) ? 256u : 0u;
#pragma unroll
            for (int kk = 0; kk < 8; kk++) {
                uint32_t af[4];
                LDMX4(af[0], af[1], af[2], af[3], a_off + abase + 32 * kk);
                uint32_t bf[4][2];
#pragma unroll
                for (int p = 0; p < 2; p++) {
                    uint32_t r0, r1, r2, r3;
                    LDMX4(r0, r1, r2, r3, b_off[p] + bbase + 32 * kk);
                    bf[2 * p][0] = r0; bf[2 * p][1] = r1;
                    bf[2 * p + 1][0] = r2; bf[2 * p + 1][1] = r3;
                }
#pragma unroll
                for (int j = 0; j < 4; j++)
                    MMA16816(s_[j], af[0], af[1], af[2], af[3], bf[j][0], bf[j][1]);
            }
        }

        // ---- online softmax ----
        const bool diag = (jt == qtile);
        float mxa = -FLT_MAX, mxb = -FLT_MAX;
#pragma unroll
        for (int j = 0; j < 4; j++)
#pragma unroll
            for (int e = 0; e < 2; e++) {
                int cg = colb + 8 * j + e;
                float va = s_[j][e] * ATT_SCALE;
                if (diag && cg > row_a) va = -FLT_MAX;
                s_[j][e] = va; mxa = fmaxf(mxa, va);
                float vb = s_[j][e + 2] * ATT_SCALE;
                if (diag && cg > row_b) vb = -FLT_MAX;
                s_[j][e + 2] = vb; mxb = fmaxf(mxb, vb);
            }
        mxa = fmaxf(mxa, __shfl_xor_sync(0xffffffffu, mxa, 1));
        mxa = fmaxf(mxa, __shfl_xor_sync(0xffffffffu, mxa, 2));
        mxb = fmaxf(mxb, __shfl_xor_sync(0xffffffffu, mxb, 1));
        mxb = fmaxf(mxb, __shfl_xor_sync(0xffffffffu, mxb, 2));
        if ((lane & 3) == 0) {
            redmax[wn * 64 + row_a] = mxa;
            redmax[wn * 64 + row_b] = mxb;
        }
        __syncthreads();
        float mna = fmaxf(m_a, fmaxf(redmax[row_a], redmax[64 + row_a]));
        float mnb = fmaxf(m_b, fmaxf(redmax[row_b], redmax[64 + row_b]));
        float fa = __expf(m_a - mna), fb = __expf(m_b - mnb);
        float sa = 0.0f, sb = 0.0f;
#pragma unroll
        for (int j = 0; j < 4; j++)
#pragma unroll
            for (int e = 0; e < 2; e++) {
                float pa = __expf(s_[j][e] - mna);
                s_[j][e] = pa; sa += pa;
                float pb = __expf(s_[j][e + 2] - mnb);
                s_[j][e + 2] = pb; sb += pb;
            }
        sa += __shfl_xor_sync(0xffffffffu, sa, 1);
        sa += __shfl_xor_sync(0xffffffffu, sa, 2);
        sb += __shfl_xor_sync(0xffffffffu, sb, 1);
        sb += __shfl_xor_sync(0xffffffffu, sb, 2);
        if ((lane & 3) == 0) {
            redsum[wn * 64 + row_a] = sa;
            redsum[wn * 64 + row_b] = sb;
        }
        __syncthreads();
        l_a = l_a * fa + redsum[row_a] + redsum[64 + row_a];
        l_b = l_b * fb + redsum[row_b] + redsum[64 + row_b];
        m_a = mna; m_b = mnb;

#pragma unroll
        for (int j = 0; j < 16; j++) {
            o[j][0] *= fa; o[j][1] *= fa;
            o[j][2] *= fb; o[j][3] *= fb;
        }

        // ---- P fragments (hi/lo) from S accumulators ----
        uint32_t php0[4], php1[4], plp0[4], plp1[4];
#pragma unroll
        for (int j = 0; j < 4; j++) {
            __nv_bfloat162 h01 = __floats2bfloat162_rn(s_[j][0], s_[j][1]);
            __nv_bfloat162 h23 = __floats2bfloat162_rn(s_[j][2], s_[j][3]);
            php0[j] = *(uint32_t*)&h01;
            php1[j] = *(uint32_t*)&h23;
            plp0[j] = packbf2(s_[j][0] - __bfloat162float(__low2bfloat16(h01)),
                              s_[j][1] - __bfloat162float(__high2bfloat16(h01)));
            plp1[j] = packbf2(s_[j][2] - __bfloat162float(__low2bfloat16(h23)),
                              s_[j][3] - __bfloat162float(__high2bfloat16(h23)));
        }

        // ---- O += P' V'  (PhVh, PlVh, PhVl) ----
#pragma unroll
        for (int seg = 0; seg < 3; seg++) {
            const bool useLo = (seg == 1);
            const uint32_t bbase = (seg == 2) ? (128u + wn * 64u) : (wn * 64u);
#pragma unroll
            for (int kk2 = 0; kk2 < 2; kk2++) {
                uint32_t a0 = useLo ? plp0[2 * kk2]     : php0[2 * kk2];
                uint32_t a1 = useLo ? plp1[2 * kk2]     : php1[2 * kk2];
                uint32_t a2 = useLo ? plp0[2 * kk2 + 1] : php0[2 * kk2 + 1];
                uint32_t a3 = useLo ? plp1[2 * kk2 + 1] : php1[2 * kk2 + 1];
                uint32_t vb[16][2];
#pragma unroll
                for (int p = 0; p < 8; p++) {
                    uint32_t r0, r1, r2, r3;
                    LDMX4(r0, r1, r2, r3, v_off[p] + bbase + 32 * kk2);
                    vb[2 * p][0] = r0; vb[2 * p][1] = r1;
                    vb[2 * p + 1][0] = r2; vb[2 * p + 1][1] = r3;
                }
#pragma unroll
                for (int j = 0; j < 16; j++)
                    MMA16816(o[j], a0, a1, a2, a3, vb[j][0], vb[j][1]);
            }
        }
    }

    // ---- epilogue: combine the two wn partial O and store ----
    __syncthreads();
    float* Ob = (float*)sm;   // reuse, stride 132 floats
    if (wn == 1) {
#pragma unroll
        for (int j = 0; j < 16; j++) {
            int col = 8 * j + 2 * (lane & 3);
            *(float2*)&Ob[row_a * 132 + col] = make_float2(o[j][0], o[j][1]);
            *(float2*)&Ob[row_b * 132 + col] = make_float2(o[j][2], o[j][3]);
        }
    }
    __syncthreads();
    if (wn == 0) {
        float inva = 1.0f / l_a, invb = 1.0f / l_b;
        float* base = y + (size_t)(b * T_ + q0) * 2048 + h * 128;
#pragma unroll
        for (int j = 0; j < 16; j++) {
            int col = 8 * j + 2 * (lane & 3);
            float2 pa = *(float2*)&Ob[row_a * 132 + col];
            float2 pb = *(float2*)&Ob[row_b * 132 + col];
            *(float2*)(base + (size_t)row_a * 2048 + col) =
                make_float2((o[j][0] + pa.x) * inva, (o[j][1] + pa.y) * inva);
            *(float2*)(base + (size_t)row_b * 2048 + col) =
                make_float2((o[j][2] + pb.x) * invb, (o[j][3] + pb.y) * invb);
        }
    }
}

// ---------------- launch ----------------
extern "C" void kernel_launch(void* const* d_in, const int* in_sizes, int n_in,
                              void* d_out, int out_size) {
    const float* x    = (const float*)d_in[0];
    const float* cosp = (const float*)d_in[1];
    const float* sinp = (const float*)d_in[2];
    const float* wq   = (const float*)d_in[3];
    const float* wk   = (const float*)d_in[4];
    const float* wv   = (const float*)d_in[5];
    const float* wo   = (const float*)d_in[6];
    float* out = (float*)d_out;

    __nv_bfloat16 *xs, *wb1, *wb2, *ys;
    float *qkv, *y;
    cudaGetSymbolAddress((void**)&xs,  g_xs);
    cudaGetSymbolAddress((void**)&wb1, g_wb1);
    cudaGetSymbolAddress((void**)&wb2, g_wb2);
    cudaGetSymbolAddress((void**)&ys,  g_ys);
    cudaGetSymbolAddress((void**)&qkv, g_qkv);
    cudaGetSymbolAddress((void**)&y,   g_y);

    cudaFuncSetAttribute(attn_mma_kernel, cudaFuncAttributeMaxDynamicSharedMemorySize, ATT_SMEM);

    dim3 tb(32, 8);
    split_a_kernel<<<(M_ * 2048 / 4) / 256, 256>>>(x, xs);
    tsplit_b_kernel<<<dim3(2048 / 32, 2048 / 32), tb>>>(wq, wb1, 2048);
    tsplit_b_kernel<<<dim3(512  / 32, 2048 / 32), tb>>>(wk, wb1 + (size_t)2048 * K3_, 512);
    tsplit_b_kernel<<<dim3(512  / 32, 2048 / 32), tb>>>(wv, wb1 + (size_t)2560 * K3_, 512);
    tsplit_b_kernel<<<dim3(2048 / 32, 2048 / 32), tb>>>(wo, wb2, 2048);

    gemm_bf16<<<dim3(3072 / 128, M_ / 128), 256>>>(xs, wb1, qkv, 3072);
    rope_rms_kernel<<<M_ * (H_ + KVH_), 32>>>(qkv, cosp, sinp);
    attn_mma_kernel<<<dim3(32, 32), 256, ATT_SMEM>>>(qkv, y);
    split_a_kernel<<<(M_ * 2048 / 4) / 256, 256>>>(y, ys);
    gemm_bf16<<<dim3(2048 / 128, M_ / 128), 256>>>(ys, wb2, out, 2048);
}

// round 5
// speedup vs baseline: 1.7771x; 1.7771x over previous
#include <cuda_runtime.h>
#include <cuda_bf16.h>
#include <math.h>
#include <float.h>
#include <stdint.h>

#define B_   2
#define T_   2048
#define C_   2048
#define H_   16
#define KVH_ 4
#define HD_  128
#define M_   (B_*T_)           // 4096
#define K3_  6144              // 3 * 2048 (split-K)
#define QKV_LD 3072

// ---------------- scratch ----------------
__device__ __nv_bfloat16 g_xs [(size_t)M_ * K3_];
__device__ __nv_bfloat16 g_wb1[(size_t)3072 * K3_];
__device__ __nv_bfloat16 g_wb2[(size_t)2048 * K3_];
__device__ __nv_bfloat16 g_ys [(size_t)M_ * K3_];
__device__ float g_qkv[(size_t)M_ * QKV_LD];
__device__ float g_y  [(size_t)M_ * 2048];
__device__ __nv_bfloat16 g_k2[(size_t)B_ * KVH_ * T_ * 256];        // [bkv][t][hi128|lo128]
__device__ __nv_bfloat16 g_vt[(size_t)B_ * KVH_ * HD_ * 2 * T_];    // [bkv][d][hi T|lo T]

// ---------------- helpers ----------------
__device__ __forceinline__ void split2(float v, __nv_bfloat16& h, __nv_bfloat16& l) {
    h = __float2bfloat16_rn(v);
    l = __float2bfloat16_rn(v - __bfloat162float(h));
}
__device__ __forceinline__ uint32_t smem_u32(const void* p) {
    uint32_t a;
    asm("{ .reg .u64 t; cvta.to.shared.u64 t, %1; cvt.u32.u64 %0, t; }" : "=r"(a) : "l"(p));
    return a;
}
__device__ __forceinline__ uint32_t packbf2(float x, float y) {
    __nv_bfloat162 t = __floats2bfloat162_rn(x, y);
    return *(uint32_t*)&t;
}
#define LDMX4(r0, r1, r2, r3, addr) \
    asm volatile("ldmatrix.sync.aligned.m8n8.x4.shared.b16 {%0,%1,%2,%3}, [%4];" \
        : "=r"(r0), "=r"(r1), "=r"(r2), "=r"(r3) : "r"(addr))
#define MMA16816(c, a0, a1, a2, a3, b0, b1) \
    asm volatile("mma.sync.aligned.m16n8k16.row.col.f32.bf16.bf16.f32 " \
        "{%0,%1,%2,%3}, {%4,%5,%6,%7}, {%8,%9}, {%0,%1,%2,%3};" \
        : "+f"((c)[0]), "+f"((c)[1]), "+f"((c)[2]), "+f"((c)[3]) \
        : "r"(a0), "r"(a1), "r"(a2), "r"(a3), "r"(b0), "r"(b1))

// ---------------- split kernels (GEMM operands) ----------------
__global__ __launch_bounds__(256)
void split_a_kernel(const float* __restrict__ src, __nv_bfloat16* __restrict__ dst) {
    int idx = blockIdx.x * 256 + threadIdx.x;
    int m = idx >> 9;
    int k = (idx & 511) << 2;
    float4 v = *(const float4*)(src + (size_t)m * 2048 + k);
    __nv_bfloat16 h0, h1, h2, h3, l0, l1, l2, l3;
    split2(v.x, h0, l0); split2(v.y, h1, l1);
    split2(v.z, h2, l2); split2(v.w, h3, l3);
    __nv_bfloat162 H0 = __halves2bfloat162(h0, h1), H1 = __halves2bfloat162(h2, h3);
    __nv_bfloat162 L0 = __halves2bfloat162(l0, l1), L1 = __halves2bfloat162(l2, l3);
    __nv_bfloat162* d0 = (__nv_bfloat162*)(dst + (size_t)m * K3_ + k);
    d0[0] = H0; d0[1] = H1;
    __nv_bfloat162* d1 = (__nv_bfloat162*)(dst + (size_t)m * K3_ + 2048 + k);
    d1[0] = L0; d1[1] = L1;
    __nv_bfloat162* d2 = (__nv_bfloat162*)(dst + (size_t)m * K3_ + 4096 + k);
    d2[0] = H0; d2[1] = H1;
}

__global__ __launch_bounds__(256)
void tsplit_b_kernel(const float* __restrict__ src, __nv_bfloat16* __restrict__ dst, int Ncols) {
    __shared__ float t[32][33];
    const int n0 = blockIdx.x * 32, k0 = blockIdx.y * 32;
    const int tx = threadIdx.x, ty = threadIdx.y;
#pragma unroll
    for (int i = 0; i < 4; i++)
        t[ty + i * 8][tx] = src[(size_t)(k0 + ty + i * 8) * Ncols + n0 + tx];
    __syncthreads();
#pragma unroll
    for (int i = 0; i < 4; i++) {
        float v = t[tx][ty + i * 8];
        __nv_bfloat16 h, l;
        split2(v, h, l);
        __nv_bfloat16* row = dst + (size_t)(n0 + ty + i * 8) * K3_ + k0 + tx;
        row[0]    = h;
        row[2048] = h;
        row[4096] = l;
    }
}

// ---------------- K split: qkv(k region, post-rope) -> K2 ----------------
__global__ __launch_bounds__(256)
void split_k_kernel(const float* __restrict__ qkv, __nv_bfloat16* __restrict__ k2) {
    int gid = blockIdx.x * 256 + threadIdx.x;     // B*T*KVH*32 total
    int row = gid >> 5;                            // (bt, kv)
    int c4  = gid & 31;
    int bt = row >> 2;
    int kv = row & 3;
    int b = bt >> 11, t = bt & (T_ - 1);
    float4 v = *(const float4*)(qkv + (size_t)bt * QKV_LD + 2048 + kv * 128 + c4 * 4);
    __nv_bfloat16 h0, h1, h2, h3, l0, l1, l2, l3;
    split2(v.x, h0, l0); split2(v.y, h1, l1);
    split2(v.z, h2, l2); split2(v.w, h3, l3);
    __nv_bfloat16* dst = k2 + ((size_t)(b * KVH_ + kv) * T_ + t) * 256 + c4 * 4;
    *(__nv_bfloat162*)(dst)           = __halves2bfloat162(h0, h1);
    *(__nv_bfloat162*)(dst + 2)       = __halves2bfloat162(h2, h3);
    *(__nv_bfloat162*)(dst + 128)     = __halves2bfloat162(l0, l1);
    *(__nv_bfloat162*)(dst + 128 + 2) = __halves2bfloat162(l2, l3);
}

// ---------------- V transpose+split: qkv(v region) -> Vt ----------------
__global__ __launch_bounds__(256)
void split_v_kernel(const float* __restrict__ qkv, __nv_bfloat16* __restrict__ vt) {
    __shared__ float tbuf[32][33];
    const int d0 = blockIdx.x * 32;               // 0..96
    const int t0 = blockIdx.y * 32;               // 0..2016
    const int bkv = blockIdx.z;                   // 0..7
    const int b = bkv >> 2, kv = bkv & 3;
    const int tx = threadIdx.x, ty = threadIdx.y; // 32 x 8
#pragma unroll
    for (int i = 0; i < 4; i++)
        tbuf[ty + i * 8][tx] =
            qkv[(size_t)(b * T_ + t0 + ty + i * 8) * QKV_LD + 2560 + kv * 128 + d0 + tx];
    __syncthreads();
#pragma unroll
    for (int i = 0; i < 4; i++) {
        float v = tbuf[tx][ty + i * 8];
        __nv_bfloat16 h, l;
        split2(v, h, l);
        __nv_bfloat16* row = vt + ((size_t)bkv * 128 + d0 + ty + i * 8) * (2 * T_) + t0 + tx;
        row[0]  = h;
        row[T_] = l;
    }
}

// ---------------- bf16 mma.sync GEMM ----------------
#define SMPAD 80

__global__ __launch_bounds__(256)
void gemm_bf16(const __nv_bfloat16* __restrict__ A, const __nv_bfloat16* __restrict__ Bt,
               float* __restrict__ C, int N) {
    __shared__ __align__(16) uint8_t sm[4 * 128 * SMPAD];
    const uint32_t smb = smem_u32(sm);

    const int tid = threadIdx.x;
    const int lane = tid & 31, wid = tid >> 5;
    const int wm = wid >> 1, wn = wid & 1;
    const int m0 = blockIdx.y * 128, n0 = blockIdx.x * 128;

    const int row_g = tid >> 2;
    const int c16   = tid & 3;

    float acc[2][8][4];
#pragma unroll
    for (int i = 0; i < 2; i++)
#pragma unroll
        for (int j = 0; j < 8; j++)
#pragma unroll
            for (int r = 0; r < 4; r++) acc[i][j][r] = 0.0f;

    const int nK = K3_ / 32;

    {
        const __nv_bfloat16* ap = A  + (size_t)(m0 + row_g) * K3_ + c16 * 8;
        const __nv_bfloat16* bp = Bt + (size_t)(n0 + row_g) * K3_ + c16 * 8;
        uint4 a0 = *(const uint4*)ap;
        uint4 a1 = *(const uint4*)(ap + (size_t)64 * K3_);
        uint4 b0 = *(const uint4*)bp;
        uint4 b1 = *(const uint4*)(bp + (size_t)64 * K3_);
        *(uint4*)(sm + row_g * SMPAD + c16 * 16)                     = a0;
        *(uint4*)(sm + (row_g + 64) * SMPAD + c16 * 16)              = a1;
        *(uint4*)(sm + 2 * 128 * SMPAD + row_g * SMPAD + c16 * 16)        = b0;
        *(uint4*)(sm + 2 * 128 * SMPAD + (row_g + 64) * SMPAD + c16 * 16) = b1;
    }
    __syncthreads();

    const int lj = lane >> 3, lr = lane & 7;
    const uint32_t a_row_off = (uint32_t)((wm * 32 + ((lj & 1) << 3) + lr) * SMPAD + ((lj >> 1) << 4));
    const uint32_t b_row_off = (uint32_t)((wn * 64 + ((lj >> 1) << 3) + lr) * SMPAD + ((lj & 1) << 4));

    for (int it = 0; it < nK; it++) {
        const int buf = it & 1;
        uint4 na0, na1, nb0, nb1;
        if (it + 1 < nK) {
            const int k0 = (it + 1) << 5;
            const __nv_bfloat16* ap = A  + (size_t)(m0 + row_g) * K3_ + k0 + c16 * 8;
            const __nv_bfloat16* bp = Bt + (size_t)(n0 + row_g) * K3_ + k0 + c16 * 8;
            na0 = *(const uint4*)ap;
            na1 = *(const uint4*)(ap + (size_t)64 * K3_);
            nb0 = *(const uint4*)bp;
            nb1 = *(const uint4*)(bp + (size_t)64 * K3_);
        }

        const uint32_t sA = smb + buf * 128 * SMPAD;
        const uint32_t sB = smb + (2 + buf) * 128 * SMPAD;
#pragma unroll
        for (int kk = 0; kk < 2; kk++) {
            uint32_t af[2][4];
#pragma unroll
            for (int i = 0; i < 2; i++)
                LDMX4(af[i][0], af[i][1], af[i][2], af[i][3],
                      sA + a_row_off + i * 16 * SMPAD + kk * 32);
            uint32_t bf[8][2];
#pragma unroll
            for (int p = 0; p < 4; p++) {
                uint32_t r0, r1, r2, r3;
                LDMX4(r0, r1, r2, r3, sB + b_row_off + p * 16 * SMPAD + kk * 32);
                bf[2 * p][0] = r0; bf[2 * p][1] = r1;
                bf[2 * p + 1][0] = r2; bf[2 * p + 1][1] = r3;
            }
#pragma unroll
            for (int i = 0; i < 2; i++)
#pragma unroll
                for (int j = 0; j < 8; j++)
                    MMA16816(acc[i][j], af[i][0], af[i][1], af[i][2], af[i][3],
                             bf[j][0], bf[j][1]);
        }
        __syncthreads();
        if (it + 1 < nK) {
            const int nbuf = (it + 1) & 1;
            uint8_t* dA = sm + nbuf * 128 * SMPAD;
            uint8_t* dB = sm + (2 + nbuf) * 128 * SMPAD;
            *(uint4*)(dA + row_g * SMPAD + c16 * 16)        = na0;
            *(uint4*)(dA + (row_g + 64) * SMPAD + c16 * 16) = na1;
            *(uint4*)(dB + row_g * SMPAD + c16 * 16)        = nb0;
            *(uint4*)(dB + (row_g + 64) * SMPAD + c16 * 16) = nb1;
            __syncthreads();
        }
    }

    const int cr = lane >> 2, cc = (lane & 3) << 1;
#pragma unroll
    for (int i = 0; i < 2; i++) {
        const int mrow = m0 + wm * 32 + i * 16 + cr;
#pragma unroll
        for (int j = 0; j < 8; j++) {
            const int col = n0 + wn * 64 + j * 8 + cc;
            *(float2*)(C + (size_t)mrow * N + col)       = make_float2(acc[i][j][0], acc[i][j][1]);
            *(float2*)(C + (size_t)(mrow + 8) * N + col) = make_float2(acc[i][j][2], acc[i][j][3]);
        }
    }
}

// ---------------- RoPE + RMSNorm ----------------
__global__ __launch_bounds__(32)
void rope_rms_kernel(float* __restrict__ qkv,
                     const float* __restrict__ cosp, const float* __restrict__ sinp) {
    const int n  = blockIdx.x;
    const int bt = n / (H_ + KVH_);
    const int hh = n - bt * (H_ + KVH_);
    float* p = qkv + (size_t)bt * QKV_LD +
               ((hh < H_) ? (size_t)hh * 128 : (size_t)(2048 + (hh - H_) * 128));
    const int t = bt & (T_ - 1);
    const int l = threadIdx.x;

    float o1[2], o2[2];
    float ss = 0.0f;
#pragma unroll
    for (int u = 0; u < 2; u++) {
        int d = l + u * 32;
        float x1 = p[d];
        float x2 = p[d + 64];
        float c = cosp[t * 64 + d];
        float s = sinp[t * 64 + d];
        o1[u] = x1 * c + x2 * s;
        o2[u] = x2 * c - x1 * s;
        ss += o1[u] * o1[u] + o2[u] * o2[u];
    }
#pragma unroll
    for (int off = 16; off > 0; off >>= 1)
        ss += __shfl_xor_sync(0xffffffffu, ss, off);
    float r = rsqrtf(ss * (1.0f / 128.0f) + 1e-5f);
#pragma unroll
    for (int u = 0; u < 2; u++) {
        int d = l + u * 32;
        p[d]      = o1[u] * r;
        p[d + 64] = o2[u] * r;
    }
}

// ---------------- tensor-core flash attention ----------------
// 64 q-rows per CTA, 8 warps (4m x 2n); K/V pre-split in global.
#define AQS 528          // Q/K smem row stride bytes ([hi 256B | lo 256B])
#define AVS 272          // Vt row stride bytes ([Vh 128B | Vl 128B])
#define SM_Q 0
#define SM_K 33792
#define SM_V 67584
#define SM_RED 102400
#define ATT_SMEM 103424
#define ATT_SCALE 0.08838834764831845f

__global__ __launch_bounds__(256)
void attn_mma_kernel(const float* __restrict__ qkv,
                     const __nv_bfloat16* __restrict__ k2,
                     const __nv_bfloat16* __restrict__ vt,
                     float* __restrict__ y) {
    extern __shared__ uint8_t sm[];
    const uint32_t smb = smem_u32(sm);
    float* redmax = (float*)(sm + SM_RED);
    float* redsum = (float*)(sm + SM_RED + 512);

    const int tid = threadIdx.x;
    const int lane = tid & 31, wid = tid >> 5;
    const int wm = wid >> 1, wn = wid & 1;
    const int qtile = 31 - blockIdx.x;
    const int bh = blockIdx.y;
    const int b  = bh >> 4;
    const int h  = bh & 15;
    const int kv = h >> 2;
    const int q0 = qtile * 64;

    const int crow = tid >> 2;
    const int cc0  = (tid & 3) * 32;

    // ---- convert Q tile once (64x128 fp32 -> hi|lo bf16) ----
    {
        const float* qp = qkv + (size_t)(b * T_ + q0 + crow) * QKV_LD + h * 128 + cc0;
        uint8_t* qrow = sm + SM_Q + crow * AQS;
#pragma unroll
        for (int i = 0; i < 8; i++) {
            float4 v = *(const float4*)(qp + i * 4);
            __nv_bfloat16 h0, h1, h2, h3, l0, l1, l2, l3;
            split2(v.x, h0, l0); split2(v.y, h1, l1);
            split2(v.z, h2, l2); split2(v.w, h3, l3);
            int c = cc0 + i * 4;
            *(__nv_bfloat162*)(qrow + 2 * c)           = __halves2bfloat162(h0, h1);
            *(__nv_bfloat162*)(qrow + 2 * c + 4)       = __halves2bfloat162(h2, h3);
            *(__nv_bfloat162*)(qrow + 256 + 2 * c)     = __halves2bfloat162(l0, l1);
            *(__nv_bfloat162*)(qrow + 256 + 2 * c + 4) = __halves2bfloat162(l2, l3);
        }
    }

    const __nv_bfloat16* k2b = k2 + (size_t)(b * KVH_ + kv) * T_ * 256;
    const __nv_bfloat16* vtb = vt + (size_t)(b * KVH_ + kv) * 128 * (2 * T_);

    // ldmatrix base addresses
    const int lj = lane >> 3, lr = lane & 7;
    const uint32_t a_off = smb + SM_Q + (uint32_t)((wm * 16 + ((lj & 1) << 3) + lr) * AQS + ((lj >> 1) << 4));
    uint32_t b_off[2];
#pragma unroll
    for (int p = 0; p < 2; p++)
        b_off[p] = smb + SM_K + (uint32_t)((wn * 32 + p * 16 + ((lj >> 1) << 3) + lr) * AQS + ((lj & 1) << 4));
    uint32_t v_off[8];
#pragma unroll
    for (int p = 0; p < 8; p++)
        v_off[p] = smb + SM_V + (uint32_t)((p * 16 + ((lj >> 1) << 3) + lr) * AVS + ((lj & 1) << 4));

    const int ra = lane >> 2;
    const int row_a = wm * 16 + ra, row_b = row_a + 8;
    const int colb = wn * 32 + 2 * (lane & 3);
    float m_a = -FLT_MAX, m_b = -FLT_MAX, l_a = 0.0f, l_b = 0.0f;

    float o[16][4];
#pragma unroll
    for (int j = 0; j < 16; j++)
#pragma unroll
        for (int r = 0; r < 4; r++) o[j][r] = 0.0f;

    // K tile load indices: 64 rows x 32 uint4
    const int krow = tid >> 2, kc = tid & 3;        // 8 uint4 per thread via loop
    // V tile load indices: 128 rows x 16 uint4
    const int vrow = tid >> 1, vc = tid & 1;        // 8 uint4 per thread via loop

    for (int jt = 0; jt <= qtile; jt++) {
        const int j0 = jt * 64;
        __syncthreads();
        // ---- load pre-split K tile: 64 rows x 512B ----
        {
            const uint4* src = (const uint4*)(k2b + (size_t)(j0 + krow) * 256);
            uint8_t* dst = sm + SM_K + krow * AQS;
#pragma unroll
            for (int i = 0; i < 8; i++) {
                int c = kc + i * 4;    // 0..31
                *(uint4*)(dst + c * 16) = src[c];
            }
        }
        // ---- load pre-split V tile: 128 d-rows x (128B hi + 128B lo) ----
        {
            const __nv_bfloat16* srow = vtb + (size_t)vrow * (2 * T_) + j0;
            uint8_t* dst = sm + SM_V + vrow * AVS;
#pragma unroll
            for (int i = 0; i < 4; i++) {
                int c = vc + i * 2;    // 0..7
                *(uint4*)(dst + c * 16)       = *(const uint4*)(srow + c * 8);
                *(uint4*)(dst + 128 + c * 16) = *(const uint4*)(srow + T_ + c * 8);
            }
        }
        __syncthreads();

        // ---- S = Q' K'^T (3 split segments) ----
        float s_[4][4];
#pragma unroll
        for (int j = 0; j < 4; j++)
#pragma unroll
            for (int r = 0; r < 4; r++) s_[j][r] = 0.0f;

#pragma unroll
        for (int seg = 0; seg < 3; seg++) {
            const uint32_t abase = (seg == 1) ? 256u : 0u;
            const uint32_t bbase = (seg == 2) ? 256u : 0u;
#pragma unroll
            for (int kk = 0; kk < 8; kk++) {
                uint32_t af[4];
                LDMX4(af[0], af[1], af[2], af[3], a_off + abase + 32 * kk);
                uint32_t bf[4][2];
#pragma unroll
                for (int p = 0; p < 2; p++) {
                    uint32_t r0, r1, r2, r3;
                    LDMX4(r0, r1, r2, r3, b_off[p] + bbase + 32 * kk);
                    bf[2 * p][0] = r0; bf[2 * p][1] = r1;
                    bf[2 * p + 1][0] = r2; bf[2 * p + 1][1] = r3;
                }
#pragma unroll
                for (int j = 0; j < 4; j++)
                    MMA16816(s_[j], af[0], af[1], af[2], af[3], bf[j][0], bf[j][1]);
            }
        }

        // ---- online softmax ----
        const bool diag = (jt == qtile);
        float mxa = -FLT_MAX, mxb = -FLT_MAX;
#pragma unroll
        for (int j = 0; j < 4; j++)
#pragma unroll
            for (int e = 0; e < 2; e++) {
                int cg = colb + 8 * j + e;
                float va = s_[j][e] * ATT_SCALE;
                if (diag && cg > row_a) va = -FLT_MAX;
                s_[j][e] = va; mxa = fmaxf(mxa, va);
                float vb = s_[j][e + 2] * ATT_SCALE;
                if (diag && cg > row_b) vb = -FLT_MAX;
                s_[j][e + 2] = vb; mxb = fmaxf(mxb, vb);
            }
        mxa = fmaxf(mxa, __shfl_xor_sync(0xffffffffu, mxa, 1));
        mxa = fmaxf(mxa, __shfl_xor_sync(0xffffffffu, mxa, 2));
        mxb = fmaxf(mxb, __shfl_xor_sync(0xffffffffu, mxb, 1));
        mxb = fmaxf(mxb, __shfl_xor_sync(0xffffffffu, mxb, 2));
        if ((lane & 3) == 0) {
            redmax[wn * 64 + row_a] = mxa;
            redmax[wn * 64 + row_b] = mxb;
        }
        __syncthreads();
        float mna = fmaxf(m_a, fmaxf(redmax[row_a], redmax[64 + row_a]));
        float mnb = fmaxf(m_b, fmaxf(redmax[row_b], redmax[64 + row_b]));
        float fa = __expf(m_a - mna), fb = __expf(m_b - mnb);
        float sa = 0.0f, sb = 0.0f;
#pragma unroll
        for (int j = 0; j < 4; j++)
#pragma unroll
            for (int e = 0; e < 2; e++) {
                float pa = __expf(s_[j][e] - mna);
                s_[j][e] = pa; sa += pa;
                float pb = __expf(s_[j][e + 2] - mnb);
                s_[j][e + 2] = pb; sb += pb;
            }
        sa += __shfl_xor_sync(0xffffffffu, sa, 1);
        sa += __shfl_xor_sync(0xffffffffu, sa, 2);
        sb += __shfl_xor_sync(0xffffffffu, sb, 1);
        sb += __shfl_xor_sync(0xffffffffu, sb, 2);
        if ((lane & 3) == 0) {
            redsum[wn * 64 + row_a] = sa;
            redsum[wn * 64 + row_b] = sb;
        }
        __syncthreads();
        l_a = l_a * fa + redsum[row_a] + redsum[64 + row_a];
        l_b = l_b * fb + redsum[row_b] + redsum[64 + row_b];
        m_a = mna; m_b = mnb;

#pragma unroll
        for (int j = 0; j < 16; j++) {
            o[j][0] *= fa; o[j][1] *= fa;
            o[j][2] *= fb; o[j][3] *= fb;
        }

        // ---- P fragments (hi/lo) ----
        uint32_t php0[4], php1[4], plp0[4], plp1[4];
#pragma unroll
        for (int j = 0; j < 4; j++) {
            __nv_bfloat162 h01 = __floats2bfloat162_rn(s_[j][0], s_[j][1]);
            __nv_bfloat162 h23 = __floats2bfloat162_rn(s_[j][2], s_[j][3]);
            php0[j] = *(uint32_t*)&h01;
            php1[j] = *(uint32_t*)&h23;
            plp0[j] = packbf2(s_[j][0] - __bfloat162float(__low2bfloat16(h01)),
                              s_[j][1] - __bfloat162float(__high2bfloat16(h01)));
            plp1[j] = packbf2(s_[j][2] - __bfloat162float(__low2bfloat16(h23)),
                              s_[j][3] - __bfloat162float(__high2bfloat16(h23)));
        }

        // ---- O += P' V' (PhVh, PlVh, PhVl) ----
#pragma unroll
        for (int seg = 0; seg < 3; seg++) {
            const bool useLo = (seg == 1);
            const uint32_t bbase = (seg == 2) ? (128u + wn * 64u) : (wn * 64u);
#pragma unroll
            for (int kk2 = 0; kk2 < 2; kk2++) {
                uint32_t a0 = useLo ? plp0[2 * kk2]     : php0[2 * kk2];
                uint32_t a1 = useLo ? plp1[2 * kk2]     : php1[2 * kk2];
                uint32_t a2 = useLo ? plp0[2 * kk2 + 1] : php0[2 * kk2 + 1];
                uint32_t a3 = useLo ? plp1[2 * kk2 + 1] : php1[2 * kk2 + 1];
                uint32_t vb[16][2];
#pragma unroll
                for (int p = 0; p < 8; p++) {
                    uint32_t r0, r1, r2, r3;
                    LDMX4(r0, r1, r2, r3, v_off[p] + bbase + 32 * kk2);
                    vb[2 * p][0] = r0; vb[2 * p][1] = r1;
                    vb[2 * p + 1][0] = r2; vb[2 * p + 1][1] = r3;
                }
#pragma unroll
                for (int j = 0; j < 16; j++)
                    MMA16816(o[j], a0, a1, a2, a3, vb[j][0], vb[j][1]);
            }
        }
    }

    // ---- epilogue ----
    __syncthreads();
    float* Ob = (float*)sm;
    if (wn == 1) {
#pragma unroll
        for (int j = 0; j < 16; j++) {
            int col = 8 * j + 2 * (lane & 3);
            *(float2*)&Ob[row_a * 132 + col] = make_float2(o[j][0], o[j][1]);
            *(float2*)&Ob[row_b * 132 + col] = make_float2(o[j][2], o[j][3]);
        }
    }
    __syncthreads();
    if (wn == 0) {
        float inva = 1.0f / l_a, invb = 1.0f / l_b;
        float* base = y + (size_t)(b * T_ + q0) * 2048 + h * 128;
#pragma unroll
        for (int j = 0; j < 16; j++) {
            int col = 8 * j + 2 * (lane & 3);
            float2 pa = *(float2*)&Ob[row_a * 132 + col];
            float2 pb = *(float2*)&Ob[row_b * 132 + col];
            *(float2*)(base + (size_t)row_a * 2048 + col) =
                make_float2((o[j][0] + pa.x) * inva, (o[j][1] + pa.y) * inva);
            *(float2*)(base + (size_t)row_b * 2048 + col) =
                make_float2((o[j][2] + pb.x) * invb, (o[j][3] + pb.y) * invb);
        }
    }
}

// ---------------- launch ----------------
extern "C" void kernel_launch(void* const* d_in, const int* in_sizes, int n_in,
                              void* d_out, int out_size) {
    const float* x    = (const float*)d_in[0];
    const float* cosp = (const float*)d_in[1];
    const float* sinp = (const float*)d_in[2];
    const float* wq   = (const float*)d_in[3];
    const float* wk   = (const float*)d_in[4];
    const float* wv   = (const float*)d_in[5];
    const float* wo   = (const float*)d_in[6];
    float* out = (float*)d_out;

    __nv_bfloat16 *xs, *wb1, *wb2, *ys, *k2, *vt;
    float *qkv, *y;
    cudaGetSymbolAddress((void**)&xs,  g_xs);
    cudaGetSymbolAddress((void**)&wb1, g_wb1);
    cudaGetSymbolAddress((void**)&wb2, g_wb2);
    cudaGetSymbolAddress((void**)&ys,  g_ys);
    cudaGetSymbolAddress((void**)&qkv, g_qkv);
    cudaGetSymbolAddress((void**)&y,   g_y);
    cudaGetSymbolAddress((void**)&k2,  g_k2);
    cudaGetSymbolAddress((void**)&vt,  g_vt);

    cudaFuncSetAttribute(attn_mma_kernel, cudaFuncAttributeMaxDynamicSharedMemorySize, ATT_SMEM);

    dim3 tb(32, 8);
    split_a_kernel<<<(M_ * 2048 / 4) / 256, 256>>>(x, xs);
    tsplit_b_kernel<<<dim3(2048 / 32, 2048 / 32), tb>>>(wq, wb1, 2048);
    tsplit_b_kernel<<<dim3(512  / 32, 2048 / 32), tb>>>(wk, wb1 + (size_t)2048 * K3_, 512);
    tsplit_b_kernel<<<dim3(512  / 32, 2048 / 32), tb>>>(wv, wb1 + (size_t)2560 * K3_, 512);
    tsplit_b_kernel<<<dim3(2048 / 32, 2048 / 32), tb>>>(wo, wb2, 2048);

    gemm_bf16<<<dim3(3072 / 128, M_ / 128), 256>>>(xs, wb1, qkv, 3072);
    rope_rms_kernel<<<M_ * (H_ + KVH_), 32>>>(qkv, cosp, sinp);
    // pre-split K and V for attention
    split_k_kernel<<<(B_ * T_ * KVH_ * 32) / 256, 256>>>(qkv, k2);
    split_v_kernel<<<dim3(4, 64, 8), tb>>>(qkv, vt);

    attn_mma_kernel<<<dim3(32, 32), 256, ATT_SMEM>>>(qkv, k2, vt, y);
    split_a_kernel<<<(M_ * 2048 / 4) / 256, 256>>>(y, ys);
    gemm_bf16<<<dim3(2048 / 128, M_ / 128), 256>>>(ys, wb2, out, 2048);
}

// round 6
// speedup vs baseline: 1.9399x; 1.0916x over previous
#include <cuda_runtime.h>
#include <cuda_bf16.h>
#include <math.h>
#include <float.h>
#include <stdint.h>

#define B_   2
#define T_   2048
#define C_   2048
#define H_   16
#define KVH_ 4
#define HD_  128
#define M_   (B_*T_)           // 4096
#define K3_  6144              // 3 * 2048 (split-K)
#define QKV_LD 3072

// ---------------- scratch ----------------
__device__ __nv_bfloat16 g_xs [(size_t)M_ * K3_];
__device__ __nv_bfloat16 g_wb1[(size_t)3072 * K3_];
__device__ __nv_bfloat16 g_wb2[(size_t)2048 * K3_];
__device__ __nv_bfloat16 g_ys [(size_t)M_ * K3_];
__device__ float g_qkv[(size_t)M_ * QKV_LD];
__device__ __nv_bfloat16 g_k2[(size_t)B_ * KVH_ * T_ * 256];        // [bkv][t][hi128|lo128]
__device__ __nv_bfloat16 g_vt[(size_t)B_ * KVH_ * HD_ * 2 * T_];    // [bkv][d][hi T|lo T]

// ---------------- helpers ----------------
__device__ __forceinline__ void split2(float v, __nv_bfloat16& h, __nv_bfloat16& l) {
    h = __float2bfloat16_rn(v);
    l = __float2bfloat16_rn(v - __bfloat162float(h));
}
__device__ __forceinline__ uint32_t smem_u32(const void* p) {
    uint32_t a;
    asm("{ .reg .u64 t; cvta.to.shared.u64 t, %1; cvt.u32.u64 %0, t; }" : "=r"(a) : "l"(p));
    return a;
}
__device__ __forceinline__ uint32_t packbf2(float x, float y) {
    __nv_bfloat162 t = __floats2bfloat162_rn(x, y);
    return *(uint32_t*)&t;
}
#define LDMX4(r0, r1, r2, r3, addr) \
    asm volatile("ldmatrix.sync.aligned.m8n8.x4.shared.b16 {%0,%1,%2,%3}, [%4];" \
        : "=r"(r0), "=r"(r1), "=r"(r2), "=r"(r3) : "r"(addr))
#define MMA16816(c, a0, a1, a2, a3, b0, b1) \
    asm volatile("mma.sync.aligned.m16n8k16.row.col.f32.bf16.bf16.f32 " \
        "{%0,%1,%2,%3}, {%4,%5,%6,%7}, {%8,%9}, {%0,%1,%2,%3};" \
        : "+f"((c)[0]), "+f"((c)[1]), "+f"((c)[2]), "+f"((c)[3]) \
        : "r"(a0), "r"(a1), "r"(a2), "r"(a3), "r"(b0), "r"(b1))
#define CP_ASYNC16(dst, src) \
    asm volatile("cp.async.cg.shared.global [%0], [%1], 16;" :: "r"(dst), "l"(src) : "memory")
#define CP_COMMIT() asm volatile("cp.async.commit_group;" ::: "memory")
#define CP_WAIT(n)  asm volatile("cp.async.wait_group %0;" :: "n"(n) : "memory")

// ---------------- split kernels ----------------
__global__ __launch_bounds__(256)
void split_a_kernel(const float* __restrict__ src, __nv_bfloat16* __restrict__ dst) {
    int idx = blockIdx.x * 256 + threadIdx.x;
    int m = idx >> 9;
    int k = (idx & 511) << 2;
    float4 v = *(const float4*)(src + (size_t)m * 2048 + k);
    __nv_bfloat16 h0, h1, h2, h3, l0, l1, l2, l3;
    split2(v.x, h0, l0); split2(v.y, h1, l1);
    split2(v.z, h2, l2); split2(v.w, h3, l3);
    __nv_bfloat162 H0 = __halves2bfloat162(h0, h1), H1 = __halves2bfloat162(h2, h3);
    __nv_bfloat162 L0 = __halves2bfloat162(l0, l1), L1 = __halves2bfloat162(l2, l3);
    __nv_bfloat162* d0 = (__nv_bfloat162*)(dst + (size_t)m * K3_ + k);
    d0[0] = H0; d0[1] = H1;
    __nv_bfloat162* d1 = (__nv_bfloat162*)(dst + (size_t)m * K3_ + 2048 + k);
    d1[0] = L0; d1[1] = L1;
    __nv_bfloat162* d2 = (__nv_bfloat162*)(dst + (size_t)m * K3_ + 4096 + k);
    d2[0] = H0; d2[1] = H1;
}

__global__ __launch_bounds__(256)
void tsplit_b_kernel(const float* __restrict__ src, __nv_bfloat16* __restrict__ dst, int Ncols) {
    __shared__ float t[32][33];
    const int n0 = blockIdx.x * 32, k0 = blockIdx.y * 32;
    const int tx = threadIdx.x, ty = threadIdx.y;
#pragma unroll
    for (int i = 0; i < 4; i++)
        t[ty + i * 8][tx] = src[(size_t)(k0 + ty + i * 8) * Ncols + n0 + tx];
    __syncthreads();
#pragma unroll
    for (int i = 0; i < 4; i++) {
        float v = t[tx][ty + i * 8];
        __nv_bfloat16 h, l;
        split2(v, h, l);
        __nv_bfloat16* row = dst + (size_t)(n0 + ty + i * 8) * K3_ + k0 + tx;
        row[0]    = h;
        row[2048] = h;
        row[4096] = l;
    }
}

// ---------------- V transpose+split ----------------
__global__ __launch_bounds__(256)
void split_v_kernel(const float* __restrict__ qkv, __nv_bfloat16* __restrict__ vt) {
    __shared__ float tbuf[32][33];
    const int d0 = blockIdx.x * 32;
    const int t0 = blockIdx.y * 32;
    const int bkv = blockIdx.z;
    const int b = bkv >> 2, kv = bkv & 3;
    const int tx = threadIdx.x, ty = threadIdx.y;
#pragma unroll
    for (int i = 0; i < 4; i++)
        tbuf[ty + i * 8][tx] =
            qkv[(size_t)(b * T_ + t0 + ty + i * 8) * QKV_LD + 2560 + kv * 128 + d0 + tx];
    __syncthreads();
#pragma unroll
    for (int i = 0; i < 4; i++) {
        float v = tbuf[tx][ty + i * 8];
        __nv_bfloat16 h, l;
        split2(v, h, l);
        __nv_bfloat16* row = vt + ((size_t)bkv * 128 + d0 + ty + i * 8) * (2 * T_) + t0 + tx;
        row[0]  = h;
        row[T_] = l;
    }
}

// ---------------- bf16 mma.sync GEMM, 4-stage cp.async pipeline ----------------
#define SMPAD 80
#define GSTAGE_B (2 * 128 * SMPAD)      // 20480 per stage (A + B)
#define GSMEM (4 * GSTAGE_B)            // 81920

__global__ __launch_bounds__(256, 2)
void gemm_bf16(const __nv_bfloat16* __restrict__ A, const __nv_bfloat16* __restrict__ Bt,
               float* __restrict__ C, int N) {
    extern __shared__ uint8_t sm[];
    const uint32_t smb = smem_u32(sm);

    const int tid = threadIdx.x;
    const int lane = tid & 31, wid = tid >> 5;
    const int wm = wid >> 1, wn = wid & 1;
    const int m0 = blockIdx.y * 128, n0 = blockIdx.x * 128;

    // copy indices: each thread does 2x16B for A and 2x16B for B per stage
    const int crow = tid >> 1;           // 0..127
    const int cc2  = (tid & 1) * 2;      // 16B-chunk base (0 or 2)
    const __nv_bfloat16* agp = A  + (size_t)(m0 + crow) * K3_ + cc2 * 8;
    const __nv_bfloat16* bgp = Bt + (size_t)(n0 + crow) * K3_ + cc2 * 8;
    const uint32_t sa_rel = (uint32_t)(crow * SMPAD + cc2 * 16);
    const uint32_t sb_rel = sa_rel + 128 * SMPAD;

    float acc[2][8][4];
#pragma unroll
    for (int i = 0; i < 2; i++)
#pragma unroll
        for (int j = 0; j < 8; j++)
#pragma unroll
            for (int r = 0; r < 4; r++) acc[i][j][r] = 0.0f;

    const int nK = K3_ / 32;   // 192

    // prologue: stages 0..2
#pragma unroll
    for (int s = 0; s < 3; s++) {
        const uint32_t base = smb + s * GSTAGE_B;
        const int k0 = s * 32;
        CP_ASYNC16(base + sa_rel,      agp + k0);
        CP_ASYNC16(base + sa_rel + 16, agp + k0 + 8);
        CP_ASYNC16(base + sb_rel,      bgp + k0);
        CP_ASYNC16(base + sb_rel + 16, bgp + k0 + 8);
        CP_COMMIT();
    }

    const int lj = lane >> 3, lr = lane & 7;
    const uint32_t a_rel = (uint32_t)((wm * 32 + ((lj & 1) << 3) + lr) * SMPAD + ((lj >> 1) << 4));
    const uint32_t b_rel = (uint32_t)(128 * SMPAD + (wn * 64 + ((lj >> 1) << 3) + lr) * SMPAD + ((lj & 1) << 4));

    for (int it = 0; it < nK; it++) {
        CP_WAIT(2);                 // stage `it` resident
        __syncthreads();            // all warps done with slot being refilled
        const int is = it + 3;
        if (is < nK) {
            const uint32_t base = smb + (is & 3) * GSTAGE_B;
            const int k0 = is * 32;
            CP_ASYNC16(base + sa_rel,      agp + k0);
            CP_ASYNC16(base + sa_rel + 16, agp + k0 + 8);
            CP_ASYNC16(base + sb_rel,      bgp + k0);
            CP_ASYNC16(base + sb_rel + 16, bgp + k0 + 8);
        }
        CP_COMMIT();

        const uint32_t stg = smb + (it & 3) * GSTAGE_B;
#pragma unroll
        for (int kk = 0; kk < 2; kk++) {
            uint32_t af[2][4];
#pragma unroll
            for (int i = 0; i < 2; i++)
                LDMX4(af[i][0], af[i][1], af[i][2], af[i][3],
                      stg + a_rel + i * 16 * SMPAD + kk * 32);
            uint32_t bf[8][2];
#pragma unroll
            for (int p = 0; p < 4; p++) {
                uint32_t r0, r1, r2, r3;
                LDMX4(r0, r1, r2, r3, stg + b_rel + p * 16 * SMPAD + kk * 32);
                bf[2 * p][0] = r0; bf[2 * p][1] = r1;
                bf[2 * p + 1][0] = r2; bf[2 * p + 1][1] = r3;
            }
#pragma unroll
            for (int i = 0; i < 2; i++)
#pragma unroll
                for (int j = 0; j < 8; j++)
                    MMA16816(acc[i][j], af[i][0], af[i][1], af[i][2], af[i][3],
                             bf[j][0], bf[j][1]);
        }
    }

    const int cr = lane >> 2, cc = (lane & 3) << 1;
#pragma unroll
    for (int i = 0; i < 2; i++) {
        const int mrow = m0 + wm * 32 + i * 16 + cr;
#pragma unroll
        for (int j = 0; j < 8; j++) {
            const int col = n0 + wn * 64 + j * 8 + cc;
            *(float2*)(C + (size_t)mrow * N + col)       = make_float2(acc[i][j][0], acc[i][j][1]);
            *(float2*)(C + (size_t)(mrow + 8) * N + col) = make_float2(acc[i][j][2], acc[i][j][3]);
        }
    }
}

// ---------------- RoPE + RMSNorm (+ fused K split) ----------------
__global__ __launch_bounds__(32)
void rope_rms_kernel(float* __restrict__ qkv,
                     const float* __restrict__ cosp, const float* __restrict__ sinp,
                     __nv_bfloat16* __restrict__ k2) {
    const int n  = blockIdx.x;
    const int bt = n / (H_ + KVH_);
    const int hh = n - bt * (H_ + KVH_);
    float* p = qkv + (size_t)bt * QKV_LD +
               ((hh < H_) ? (size_t)hh * 128 : (size_t)(2048 + (hh - H_) * 128));
    const int t = bt & (T_ - 1);
    const int l = threadIdx.x;

    float o1[2], o2[2];
    float ss = 0.0f;
#pragma unroll
    for (int u = 0; u < 2; u++) {
        int d = l + u * 32;
        float x1 = p[d];
        float x2 = p[d + 64];
        float c = cosp[t * 64 + d];
        float s = sinp[t * 64 + d];
        o1[u] = x1 * c + x2 * s;
        o2[u] = x2 * c - x1 * s;
        ss += o1[u] * o1[u] + o2[u] * o2[u];
    }
#pragma unroll
    for (int off = 16; off > 0; off >>= 1)
        ss += __shfl_xor_sync(0xffffffffu, ss, off);
    float r = rsqrtf(ss * (1.0f / 128.0f) + 1e-5f);
#pragma unroll
    for (int u = 0; u < 2; u++) {
        int d = l + u * 32;
        p[d]      = o1[u] * r;
        p[d + 64] = o2[u] * r;
    }
    if (hh >= H_) {
        // fused K split into k2 [bkv][t][hi128|lo128]
        const int kvh = hh - H_;
        const int b = bt >> 11;
        __nv_bfloat16* krow = k2 + ((size_t)(b * KVH_ + kvh) * T_ + t) * 256;
#pragma unroll
        for (int u = 0; u < 2; u++) {
            int d = l + u * 32;
            __nv_bfloat16 h1, l1, h2, l2;
            split2(o1[u] * r, h1, l1);
            split2(o2[u] * r, h2, l2);
            krow[d]            = h1;
            krow[128 + d]      = l1;
            krow[d + 64]       = h2;
            krow[128 + d + 64] = l2;
        }
    }
}

// ---------------- tensor-core flash attention ----------------
#define AQS 528
#define AVS 272
#define SM_Q 0
#define SM_K 33792
#define SM_V 67584
#define SM_RED 102400
#define ATT_SMEM 103424
#define ATT_SCALE 0.08838834764831845f

__global__ __launch_bounds__(256)
void attn_mma_kernel(const float* __restrict__ qkv,
                     const __nv_bfloat16* __restrict__ k2,
                     const __nv_bfloat16* __restrict__ vt,
                     __nv_bfloat16* __restrict__ ys) {
    extern __shared__ uint8_t sm[];
    const uint32_t smb = smem_u32(sm);
    float* redmax = (float*)(sm + SM_RED);
    float* redsum = (float*)(sm + SM_RED + 512);

    const int tid = threadIdx.x;
    const int lane = tid & 31, wid = tid >> 5;
    const int wm = wid >> 1, wn = wid & 1;
    const int qtile = 31 - blockIdx.x;
    const int bh = blockIdx.y;
    const int b  = bh >> 4;
    const int h  = bh & 15;
    const int kv = h >> 2;
    const int q0 = qtile * 64;

    const int crow = tid >> 2;
    const int cc0  = (tid & 3) * 32;

    // ---- convert Q tile once ----
    {
        const float* qp = qkv + (size_t)(b * T_ + q0 + crow) * QKV_LD + h * 128 + cc0;
        uint8_t* qrow = sm + SM_Q + crow * AQS;
#pragma unroll
        for (int i = 0; i < 8; i++) {
            float4 v = *(const float4*)(qp + i * 4);
            __nv_bfloat16 h0, h1, h2, h3, l0, l1, l2, l3;
            split2(v.x, h0, l0); split2(v.y, h1, l1);
            split2(v.z, h2, l2); split2(v.w, h3, l3);
            int c = cc0 + i * 4;
            *(__nv_bfloat162*)(qrow + 2 * c)           = __halves2bfloat162(h0, h1);
            *(__nv_bfloat162*)(qrow + 2 * c + 4)       = __halves2bfloat162(h2, h3);
            *(__nv_bfloat162*)(qrow + 256 + 2 * c)     = __halves2bfloat162(l0, l1);
            *(__nv_bfloat162*)(qrow + 256 + 2 * c + 4) = __halves2bfloat162(l2, l3);
        }
    }

    const __nv_bfloat16* k2b = k2 + (size_t)(b * KVH_ + kv) * T_ * 256;
    const __nv_bfloat16* vtb = vt + (size_t)(b * KVH_ + kv) * 128 * (2 * T_);

    const int lj = lane >> 3, lr = lane & 7;
    const uint32_t a_off = smb + SM_Q + (uint32_t)((wm * 16 + ((lj & 1) << 3) + lr) * AQS + ((lj >> 1) << 4));
    uint32_t b_off[2];
#pragma unroll
    for (int p = 0; p < 2; p++)
        b_off[p] = smb + SM_K + (uint32_t)((wn * 32 + p * 16 + ((lj >> 1) << 3) + lr) * AQS + ((lj & 1) << 4));
    uint32_t v_off[8];
#pragma unroll
    for (int p = 0; p < 8; p++)
        v_off[p] = smb + SM_V + (uint32_t)((p * 16 + ((lj >> 1) << 3) + lr) * AVS + ((lj & 1) << 4));

    const int ra = lane >> 2;
    const int row_a = wm * 16 + ra, row_b = row_a + 8;
    const int colb = wn * 32 + 2 * (lane & 3);
    float m_a = -FLT_MAX, m_b = -FLT_MAX, l_a = 0.0f, l_b = 0.0f;

    float o[16][4];
#pragma unroll
    for (int j = 0; j < 16; j++)
#pragma unroll
        for (int r = 0; r < 4; r++) o[j][r] = 0.0f;

    const int krow = tid >> 2, kc = tid & 3;
    const int vrow = tid >> 1, vc = tid & 1;

    for (int jt = 0; jt <= qtile; jt++) {
        const int j0 = jt * 64;
        __syncthreads();
        {
            const uint4* src = (const uint4*)(k2b + (size_t)(j0 + krow) * 256);
            uint8_t* dst = sm + SM_K + krow * AQS;
#pragma unroll
            for (int i = 0; i < 8; i++) {
                int c = kc + i * 4;
                *(uint4*)(dst + c * 16) = src[c];
            }
        }
        {
            const __nv_bfloat16* srow = vtb + (size_t)vrow * (2 * T_) + j0;
            uint8_t* dst = sm + SM_V + vrow * AVS;
#pragma unroll
            for (int i = 0; i < 4; i++) {
                int c = vc + i * 2;
                *(uint4*)(dst + c * 16)       = *(const uint4*)(srow + c * 8);
                *(uint4*)(dst + 128 + c * 16) = *(const uint4*)(srow + T_ + c * 8);
            }
        }
        __syncthreads();

        float s_[4][4];
#pragma unroll
        for (int j = 0; j < 4; j++)
#pragma unroll
            for (int r = 0; r < 4; r++) s_[j][r] = 0.0f;

#pragma unroll
        for (int seg = 0; seg < 3; seg++) {
            const uint32_t abase = (seg == 1) ? 256u : 0u;
            const uint32_t bbase = (seg == 2) ? 256u : 0u;
#pragma unroll
            for (int kk = 0; kk < 8; kk++) {
                uint32_t af[4];
                LDMX4(af[0], af[1], af[2], af[3], a_off + abase + 32 * kk);
                uint32_t bf[4][2];
#pragma unroll
                for (int p = 0; p < 2; p++) {
                    uint32_t r0, r1, r2, r3;
                    LDMX4(r0, r1, r2, r3, b_off[p] + bbase + 32 * kk);
                    bf[2 * p][0] = r0; bf[2 * p][1] = r1;
                    bf[2 * p + 1][0] = r2; bf[2 * p + 1][1] = r3;
                }
#pragma unroll
                for (int j = 0; j < 4; j++)
                    MMA16816(s_[j], af[0], af[1], af[2], af[3], bf[j][0], bf[j][1]);
            }
        }

        const bool diag = (jt == qtile);
        float mxa = -FLT_MAX, mxb = -FLT_MAX;
#pragma unroll
        for (int j = 0; j < 4; j++)
#pragma unroll
            for (int e = 0; e < 2; e++) {
                int cg = colb + 8 * j + e;
                float va = s_[j][e] * ATT_SCALE;
                if (diag && cg > row_a) va = -FLT_MAX;
                s_[j][e] = va; mxa = fmaxf(mxa, va);
                float vb = s_[j][e + 2] * ATT_SCALE;
                if (diag && cg > row_b) vb = -FLT_MAX;
                s_[j][e + 2] = vb; mxb = fmaxf(mxb, vb);
            }
        mxa = fmaxf(mxa, __shfl_xor_sync(0xffffffffu, mxa, 1));
        mxa = fmaxf(mxa, __shfl_xor_sync(0xffffffffu, mxa, 2));
        mxb = fmaxf(mxb, __shfl_xor_sync(0xffffffffu, mxb, 1));
        mxb = fmaxf(mxb, __shfl_xor_sync(0xffffffffu, mxb, 2));
        if ((lane & 3) == 0) {
            redmax[wn * 64 + row_a] = mxa;
            redmax[wn * 64 + row_b] = mxb;
        }
        __syncthreads();
        float mna = fmaxf(m_a, fmaxf(redmax[row_a], redmax[64 + row_a]));
        float mnb = fmaxf(m_b, fmaxf(redmax[row_b], redmax[64 + row_b]));
        float fa = __expf(m_a - mna), fb = __expf(m_b - mnb);
        float sa = 0.0f, sb = 0.0f;
#pragma unroll
        for (int j = 0; j < 4; j++)
#pragma unroll
            for (int e = 0; e < 2; e++) {
                float pa = __expf(s_[j][e] - mna);
                s_[j][e] = pa; sa += pa;
                float pb = __expf(s_[j][e + 2] - mnb);
                s_[j][e + 2] = pb; sb += pb;
            }
        sa += __shfl_xor_sync(0xffffffffu, sa, 1);
        sa += __shfl_xor_sync(0xffffffffu, sa, 2);
        sb += __shfl_xor_sync(0xffffffffu, sb, 1);
        sb += __shfl_xor_sync(0xffffffffu, sb, 2);
        if ((lane & 3) == 0) {
            redsum[wn * 64 + row_a] = sa;
            redsum[wn * 64 + row_b] = sb;
        }
        __syncthreads();
        l_a = l_a * fa + redsum[row_a] + redsum[64 + row_a];
        l_b = l_b * fb + redsum[row_b] + redsum[64 + row_b];
        m_a = mna; m_b = mnb;

#pragma unroll
        for (int j = 0; j < 16; j++) {
            o[j][0] *= fa; o[j][1] *= fa;
            o[j][2] *= fb; o[j][3] *= fb;
        }

        uint32_t php0[4], php1[4], plp0[4], plp1[4];
#pragma unroll
        for (int j = 0; j < 4; j++) {
            __nv_bfloat162 h01 = __floats2bfloat162_rn(s_[j][0], s_[j][1]);
            __nv_bfloat162 h23 = __floats2bfloat162_rn(s_[j][2], s_[j][3]);
            php0[j] = *(uint32_t*)&h01;
            php1[j] = *(uint32_t*)&h23;
            plp0[j] = packbf2(s_[j][0] - __bfloat162float(__low2bfloat16(h01)),
                              s_[j][1] - __bfloat162float(__high2bfloat16(h01)));
            plp1[j] = packbf2(s_[j][2] - __bfloat162float(__low2bfloat16(h23)),
                              s_[j][3] - __bfloat162float(__high2bfloat16(h23)));
        }

#pragma unroll
        for (int seg = 0; seg < 3; seg++) {
            const bool useLo = (seg == 1);
            const uint32_t bbase = (seg == 2) ? (128u + wn * 64u) : (wn * 64u);
#pragma unroll
            for (int kk2 = 0; kk2 < 2; kk2++) {
                uint32_t a0 = useLo ? plp0[2 * kk2]     : php0[2 * kk2];
                uint32_t a1 = useLo ? plp1[2 * kk2]     : php1[2 * kk2];
                uint32_t a2 = useLo ? plp0[2 * kk2 + 1] : php0[2 * kk2 + 1];
                uint32_t a3 = useLo ? plp1[2 * kk2 + 1] : php1[2 * kk2 + 1];
                uint32_t vb[16][2];
#pragma unroll
                for (int p = 0; p < 8; p++) {
                    uint32_t r0, r1, r2, r3;
                    LDMX4(r0, r1, r2, r3, v_off[p] + bbase + 32 * kk2);
                    vb[2 * p][0] = r0; vb[2 * p][1] = r1;
                    vb[2 * p + 1][0] = r2; vb[2 * p + 1][1] = r3;
                }
#pragma unroll
                for (int j = 0; j < 16; j++)
                    MMA16816(o[j], a0, a1, a2, a3, vb[j][0], vb[j][1]);
            }
        }
    }

    // ---- epilogue: combine partials, write split ys directly ----
    __syncthreads();
    float* Ob = (float*)sm;
    if (wn == 1) {
#pragma unroll
        for (int j = 0; j < 16; j++) {
            int col = 8 * j + 2 * (lane & 3);
            *(float2*)&Ob[row_a * 132 + col] = make_float2(o[j][0], o[j][1]);
            *(float2*)&Ob[row_b * 132 + col] = make_float2(o[j][2], o[j][3]);
        }
    }
    __syncthreads();
    if (wn == 0) {
        float inva = 1.0f / l_a, invb = 1.0f / l_b;
        __nv_bfloat16* base = ys + (size_t)(b * T_ + q0) * K3_ + h * 128;
#pragma unroll
        for (int j = 0; j < 16; j++) {
            int col = 8 * j + 2 * (lane & 3);
            float2 pa = *(float2*)&Ob[row_a * 132 + col];
            float2 pb = *(float2*)&Ob[row_b * 132 + col];
            float va0 = (o[j][0] + pa.x) * inva, va1 = (o[j][1] + pa.y) * inva;
            float vb0 = (o[j][2] + pb.x) * invb, vb1 = (o[j][3] + pb.y) * invb;
            __nv_bfloat16 h0, l0, h1, l1;
            split2(va0, h0, l0); split2(va1, h1, l1);
            __nv_bfloat16* rp = base + (size_t)row_a * K3_ + col;
            *(__nv_bfloat162*)(rp)        = __halves2bfloat162(h0, h1);
            *(__nv_bfloat162*)(rp + 2048) = __halves2bfloat162(l0, l1);
            *(__nv_bfloat162*)(rp + 4096) = __halves2bfloat162(h0, h1);
            split2(vb0, h0, l0); split2(vb1, h1, l1);
            rp = base + (size_t)row_b * K3_ + col;
            *(__nv_bfloat162*)(rp)        = __halves2bfloat162(h0, h1);
            *(__nv_bfloat162*)(rp + 2048) = __halves2bfloat162(l0, l1);
            *(__nv_bfloat162*)(rp + 4096) = __halves2bfloat162(h0, h1);
        }
    }
}

// ---------------- launch ----------------
extern "C" void kernel_launch(void* const* d_in, const int* in_sizes, int n_in,
                              void* d_out, int out_size) {
    const float* x    = (const float*)d_in[0];
    const float* cosp = (const float*)d_in[1];
    const float* sinp = (const float*)d_in[2];
    const float* wq   = (const float*)d_in[3];
    const float* wk   = (const float*)d_in[4];
    const float* wv   = (const float*)d_in[5];
    const float* wo   = (const float*)d_in[6];
    float* out = (float*)d_out;

    __nv_bfloat16 *xs, *wb1, *wb2, *ys, *k2, *vt;
    float *qkv;
    cudaGetSymbolAddress((void**)&xs,  g_xs);
    cudaGetSymbolAddress((void**)&wb1, g_wb1);
    cudaGetSymbolAddress((void**)&wb2, g_wb2);
    cudaGetSymbolAddress((void**)&ys,  g_ys);
    cudaGetSymbolAddress((void**)&qkv, g_qkv);
    cudaGetSymbolAddress((void**)&k2,  g_k2);
    cudaGetSymbolAddress((void**)&vt,  g_vt);

    cudaFuncSetAttribute(attn_mma_kernel, cudaFuncAttributeMaxDynamicSharedMemorySize, ATT_SMEM);
    cudaFuncSetAttribute(gemm_bf16, cudaFuncAttributeMaxDynamicSharedMemorySize, GSMEM);

    dim3 tb(32, 8);
    split_a_kernel<<<(M_ * 2048 / 4) / 256, 256>>>(x, xs);
    tsplit_b_kernel<<<dim3(2048 / 32, 2048 / 32), tb>>>(wq, wb1, 2048);
    tsplit_b_kernel<<<dim3(512  / 32, 2048 / 32), tb>>>(wk, wb1 + (size_t)2048 * K3_, 512);
    tsplit_b_kernel<<<dim3(512  / 32, 2048 / 32), tb>>>(wv, wb1 + (size_t)2560 * K3_, 512);
    tsplit_b_kernel<<<dim3(2048 / 32, 2048 / 32), tb>>>(wo, wb2, 2048);

    gemm_bf16<<<dim3(3072 / 128, M_ / 128), 256, GSMEM>>>(xs, wb1, qkv, 3072);
    rope_rms_kernel<<<M_ * (H_ + KVH_), 32>>>(qkv, cosp, sinp, k2);
    split_v_kernel<<<dim3(4, 64, 8), tb>>>(qkv, vt);

    attn_mma_kernel<<<dim3(32, 32), 256, ATT_SMEM>>>(qkv, k2, vt, ys);
    gemm_bf16<<<dim3(2048 / 128, M_ / 128), 256, GSMEM>>>(ys, wb2, out, 2048);
}